// round 1
// baseline (speedup 1.0000x reference)
#include <cuda_runtime.h>
#include <cuda_bf16.h>

#define KS 7
#define KK 49
#define TPB 128

__device__ __forceinline__ float cubic_w(float x) {
    // a = -0.5 bicubic kernel, matches reference piecewise polynomial.
    float ax = fabsf(x);
    // |x| <= 1 : 1.5 ax^3 - 2.5 ax^2 + 1
    float p1 = fmaf(fmaf(1.5f, ax, -2.5f), ax * ax, 1.0f);
    // 1 < |x| <= 2 : -0.5 ax^3 + 2.5 ax^2 - 4 ax + 2
    float p2 = fmaf(fmaf(fmaf(-0.5f, ax, 2.5f), ax, -4.0f), ax, 2.0f);
    float r = (ax <= 1.0f) ? p1 : ((ax <= 2.0f) ? p2 : 0.0f);
    return r;
}

__global__ __launch_bounds__(TPB)
void kest_kernel(const float* __restrict__ m,
                 const float* __restrict__ grid,
                 const int*   __restrict__ Wp,
                 const int*   __restrict__ yi,
                 float*       __restrict__ out,
                 int N)
{
    __shared__ float w_s[TPB * KK];   // [pixel_in_block][49], stride 49 (odd -> bank-conflict-free STS)
    __shared__ float inv_s[TPB];

    const int t = threadIdx.x;
    const int n = blockIdx.x * TPB + t;

    if (n < N) {
        // homography (broadcast L1 hits)
        const float m00 = __ldg(m + 0), m01 = __ldg(m + 1), m02 = __ldg(m + 2);
        const float m10 = __ldg(m + 3), m11 = __ldg(m + 4), m12 = __ldg(m + 5);
        const float m20 = __ldg(m + 6), m21 = __ldg(m + 7), m22 = __ldg(m + 8);
        const unsigned W = (unsigned)__ldg(Wp);

        const unsigned p = (unsigned)__ldg(yi + n);
        const float px = (float)(p % W);
        const float py = (float)(p / W);

        // 4 projective samples (finite differences, same as reference)
        float plx, ply, prx, pry, ptx, pty, pbx, pby;
        {
            float x, y, X, Y, Z, iz;
            x = px - 0.5f; y = py;
            X = m00 * x + m01 * y + m02; Y = m10 * x + m11 * y + m12; Z = m20 * x + m21 * y + m22;
            iz = 1.0f / Z; plx = X * iz; ply = Y * iz;
            x = px + 0.5f; y = py;
            X = m00 * x + m01 * y + m02; Y = m10 * x + m11 * y + m12; Z = m20 * x + m21 * y + m22;
            iz = 1.0f / Z; prx = X * iz; pry = Y * iz;
            x = px; y = py - 0.5f;
            X = m00 * x + m01 * y + m02; Y = m10 * x + m11 * y + m12; Z = m20 * x + m21 * y + m22;
            iz = 1.0f / Z; ptx = X * iz; pty = Y * iz;
            x = px; y = py + 0.5f;
            X = m00 * x + m01 * y + m02; Y = m10 * x + m11 * y + m12; Z = m20 * x + m21 * y + m22;
            iz = 1.0f / Z; pbx = X * iz; pby = Y * iz;
        }

        float du0 = pbx - ptx, du1 = pby - pty;   // du = pb - pt
        float dv0 = prx - plx, dv1 = pry - ply;   // dv = pr - pl

        float len_du = sqrtf(du0 * du0 + du1 * du1);
        if (len_du < 1.0f) { du0 /= len_du; du1 /= len_du; len_du = 1.0f; }
        float len_dv = sqrtf(dv0 * dv0 + dv1 * dv1);
        if (len_dv < 1.0f) { dv0 /= len_dv; dv1 /= len_dv; len_dv = 1.0f; }

        const float det = du0 * dv1 - du1 * dv0;
        const float ild = 1.0f / (len_du * det);
        const float ilv = 1.0f / (len_dv * det);

        // x[ky][kx] = Axx*wx[kx] + Axy*wy[ky]
        // y[ky][kx] = Cxx*wx[kx] + Dyy*wy[ky]
        const float Axx = du0 * dv1 * ild - du1 * dv0 * ilv;
        const float Axy = du0 * du1 * (ilv - ild);
        const float Cxx = dv0 * dv1 * (ild - ilv);
        const float Dyy = dv1 * du0 * ilv - dv0 * du1 * ild;

        const float gx = __ldg(grid + n);
        const float gy = __ldg(grid + N + n);
        const float posx = gx + 0.5f;              // grid + 1 - offset, offset = 0.5
        const float posy = gy + 0.5f;
        const float fx = posx - floorf(posx);
        const float fy = posy - floorf(posy);

        float A[KS], C[KS], B[KS], D[KS];
        #pragma unroll
        for (int k = 0; k < KS; k++) {
            // pos_w[k] = -2.5 + k  ->  w = frac - pos_w = frac + 2.5 - k
            float wxk = fx + 2.5f - (float)k;
            float wyk = fy + 2.5f - (float)k;
            A[k] = Axx * wxk;
            C[k] = Cxx * wxk;
            B[k] = Axy * wyk;
            D[k] = Dyy * wyk;
        }

        float sum = 0.0f;
        float* wrow = &w_s[t * KK];
        #pragma unroll
        for (int ky = 0; ky < KS; ky++) {
            #pragma unroll
            for (int kx = 0; kx < KS; kx++) {
                float xx = A[kx] + B[ky];
                float yy = C[kx] + D[ky];
                float w = cubic_w(xx) * cubic_w(yy);
                sum += w;
                wrow[ky * KS + kx] = w;
            }
        }
        inv_s[t] = 1.0f / sum;
    }

    __syncthreads();

    // Coalesced vectorized write-out: SMEM is already in output order for this block.
    const long long base = (long long)blockIdx.x * (TPB * KK);
    const int valid_pix = min(TPB, N - blockIdx.x * TPB);
    if (valid_pix <= 0) return;
    const int count = valid_pix * KK;     // floats this block contributes
    const int n4 = count >> 2;

    const float4* s4 = (const float4*)w_s;
    float4* o4 = (float4*)(out + base);   // base*4 bytes is a multiple of 16 (TPB*KK*4 = 25088)

    for (int f = t; f < n4; f += TPB) {
        float4 v = s4[f];
        int i0 = 4 * f;
        v.x *= inv_s[(i0    ) / KK];
        v.y *= inv_s[(i0 + 1) / KK];
        v.z *= inv_s[(i0 + 2) / KK];
        v.w *= inv_s[(i0 + 3) / KK];
        o4[f] = v;
    }
    // tail (only possible for a partial last block; full blocks have count % 4 == 0)
    for (int i = (n4 << 2) + t; i < count; i += TPB) {
        out[base + i] = w_s[i] * inv_s[i / KK];
    }
}

extern "C" void kernel_launch(void* const* d_in, const int* in_sizes, int n_in,
                              void* d_out, int out_size) {
    // metadata order: m_inverse (9), grid (2N), H (1), W (1), yi (N)
    const float* m    = (const float*)d_in[0];
    const float* grid = (const float*)d_in[1];
    const int*   Wp   = (const int*)d_in[3];
    const int*   yi   = (const int*)d_in[4];
    float* out = (float*)d_out;

    const int N = in_sizes[4];
    const int blocks = (N + TPB - 1) / TPB;
    kest_kernel<<<blocks, TPB>>>(m, grid, Wp, yi, out, N);
}

// round 2
// speedup vs baseline: 1.1897x; 1.1897x over previous
#include <cuda_runtime.h>
#include <cuda_bf16.h>

#define KS 7
#define KK 49
#define TPB 128

// Keys bicubic (a = -0.5), branch-free, all fma-pipe:
//   cubic(x) = u^2*(1-2u) + v^2*(4v-2),  u = sat(1-|x|), v = sat(1-|x|/2)
// Verified identical to the piecewise form on [0,1], (1,2], (2,inf).
__device__ __forceinline__ float cubic_w(float x) {
    float ax = fabsf(x);
    float u = __saturatef(1.0f - ax);               // FADD.SAT with |x| modifier
    float v = __saturatef(fmaf(ax, -0.5f, 1.0f));   // FFMA.SAT, imm multiplier
    float pu = fmaf(u, -2.0f, 1.0f);                // 1-2u  (imm multiplier)
    float pv = fmaf(v,  4.0f, -2.0f);               // 4v-2  (imm multiplier)
    return fmaf(v * v, pv, (u * u) * pu);
}

__global__ __launch_bounds__(TPB)
void kest_kernel(const float* __restrict__ m,
                 const float* __restrict__ grid,
                 const int*   __restrict__ Wp,
                 const int*   __restrict__ yi,
                 float*       __restrict__ out,
                 int N)
{
    __shared__ float w_s[TPB * KK];   // [pixel_in_block][49], stride 49 (odd -> conflict-free STS)
    __shared__ float inv_s[TPB];

    const int t = threadIdx.x;
    const int n = blockIdx.x * TPB + t;

    if (n < N) {
        const float m00 = __ldg(m + 0), m01 = __ldg(m + 1), m02 = __ldg(m + 2);
        const float m10 = __ldg(m + 3), m11 = __ldg(m + 4), m12 = __ldg(m + 5);
        const float m20 = __ldg(m + 6), m21 = __ldg(m + 7), m22 = __ldg(m + 8);
        const unsigned W = (unsigned)__ldg(Wp);

        const unsigned p = (unsigned)__ldg(yi + n);
        unsigned pxi, pyi_;
        if ((W & (W - 1u)) == 0u) {               // uniform branch: power-of-two W
            const int sh = __ffs((int)W) - 1;
            pxi = p & (W - 1u);
            pyi_ = p >> sh;
        } else {
            pyi_ = p / W;
            pxi = p - pyi_ * W;
        }
        const float px = (float)pxi;
        const float py = (float)pyi_;

        // 4 projective samples (finite differences, same as reference)
        float plx, ply, prx, pry, ptx, pty, pbx, pby;
        {
            float x, y, X, Y, Z, iz;
            x = px - 0.5f; y = py;
            X = m00 * x + m01 * y + m02; Y = m10 * x + m11 * y + m12; Z = m20 * x + m21 * y + m22;
            iz = 1.0f / Z; plx = X * iz; ply = Y * iz;
            x = px + 0.5f; y = py;
            X = m00 * x + m01 * y + m02; Y = m10 * x + m11 * y + m12; Z = m20 * x + m21 * y + m22;
            iz = 1.0f / Z; prx = X * iz; pry = Y * iz;
            x = px; y = py - 0.5f;
            X = m00 * x + m01 * y + m02; Y = m10 * x + m11 * y + m12; Z = m20 * x + m21 * y + m22;
            iz = 1.0f / Z; ptx = X * iz; pty = Y * iz;
            x = px; y = py + 0.5f;
            X = m00 * x + m01 * y + m02; Y = m10 * x + m11 * y + m12; Z = m20 * x + m21 * y + m22;
            iz = 1.0f / Z; pbx = X * iz; pby = Y * iz;
        }

        float du0 = pbx - ptx, du1 = pby - pty;
        float dv0 = prx - plx, dv1 = pry - ply;

        float len_du = sqrtf(du0 * du0 + du1 * du1);
        if (len_du < 1.0f) { du0 /= len_du; du1 /= len_du; len_du = 1.0f; }
        float len_dv = sqrtf(dv0 * dv0 + dv1 * dv1);
        if (len_dv < 1.0f) { dv0 /= len_dv; dv1 /= len_dv; len_dv = 1.0f; }

        const float det = du0 * dv1 - du1 * dv0;
        const float ild = 1.0f / (len_du * det);
        const float ilv = 1.0f / (len_dv * det);

        // x[ky][kx] = Axx*wx[kx] + Axy*wy[ky] ;  y[ky][kx] = Cxx*wx[kx] + Dyy*wy[ky]
        const float Axx = du0 * dv1 * ild - du1 * dv0 * ilv;
        const float Axy = du0 * du1 * (ilv - ild);
        const float Cxx = dv0 * dv1 * (ild - ilv);
        const float Dyy = dv1 * du0 * ilv - dv0 * du1 * ild;

        const float gx = __ldg(grid + n);
        const float gy = __ldg(grid + N + n);
        const float posx = gx + 0.5f;
        const float posy = gy + 0.5f;
        const float fx = posx - floorf(posx);
        const float fy = posy - floorf(posy);

        float A[KS], C[KS], B[KS], D[KS];
        #pragma unroll
        for (int k = 0; k < KS; k++) {
            float wxk = fx + 2.5f - (float)k;
            float wyk = fy + 2.5f - (float)k;
            A[k] = Axx * wxk;
            C[k] = Cxx * wxk;
            B[k] = Axy * wyk;
            D[k] = Dyy * wyk;
        }

        // two partial sums to shorten the dependency chain
        float sum0 = 0.0f, sum1 = 0.0f;
        float* wrow = &w_s[t * KK];
        #pragma unroll
        for (int ky = 0; ky < KS; ky++) {
            const float Bk = B[ky], Dk = D[ky];
            #pragma unroll
            for (int kx = 0; kx < KS; kx++) {
                float xx = A[kx] + Bk;
                float yy = C[kx] + Dk;
                float w = cubic_w(xx) * cubic_w(yy);
                if (kx & 1) sum1 += w; else sum0 += w;
                wrow[ky * KS + kx] = w;
            }
        }
        inv_s[t] = 1.0f / (sum0 + sum1);
    }

    __syncthreads();

    // Coalesced vectorized write-out; SMEM already in output order for this block.
    const long long base = (long long)blockIdx.x * (TPB * KK);
    const int valid_pix = min(TPB, N - blockIdx.x * TPB);
    if (valid_pix <= 0) return;
    const int count = valid_pix * KK;
    const int n4 = count >> 2;

    const float4* s4 = (const float4*)w_s;
    float4* o4 = (float4*)(out + base);

    for (int f = t; f < n4; f += TPB) {
        float4 v = s4[f];
        unsigned i0 = 4u * (unsigned)f;
        unsigned q = i0 / 49u;                 // single magic-mul divide
        unsigned r = i0 - q * 49u;
        float inv0 = inv_s[q];
        float inv1 = inv_s[q + (r >= 48u)];
        float inv2 = inv_s[q + (r >= 47u)];
        float inv3 = inv_s[q + (r >= 46u)];
        v.x *= inv0; v.y *= inv1; v.z *= inv2; v.w *= inv3;
        o4[f] = v;
    }
    for (int i = (n4 << 2) + t; i < count; i += TPB) {
        out[base + i] = w_s[i] * inv_s[(unsigned)i / 49u];
    }
}

extern "C" void kernel_launch(void* const* d_in, const int* in_sizes, int n_in,
                              void* d_out, int out_size) {
    // metadata order: m_inverse (9), grid (2N), H (1), W (1), yi (N)
    const float* m    = (const float*)d_in[0];
    const float* grid = (const float*)d_in[1];
    const int*   Wp   = (const int*)d_in[3];
    const int*   yi   = (const int*)d_in[4];
    float* out = (float*)d_out;

    const int N = in_sizes[4];
    const int blocks = (N + TPB - 1) / TPB;
    kest_kernel<<<blocks, TPB>>>(m, grid, Wp, yi, out, N);
}

// round 3
// speedup vs baseline: 1.2800x; 1.0759x over previous
#include <cuda_runtime.h>
#include <cuda_bf16.h>

#define KS 7
#define KK 49
#define TPB 128

// Keys bicubic (a=-0.5), branch-free: cubic(x) = u^2(1-2u) + v^2(4v-2),
// u = sat(1-|x|), v = sat(1-|x|/2). C1-continuous.
__device__ __forceinline__ float cubic_w(float x) {
    float ax = fabsf(x);
    float u = __saturatef(1.0f - ax);
    float v = __saturatef(fmaf(ax, -0.5f, 1.0f));
    float pu = fmaf(u, -2.0f, 1.0f);
    float pv = fmaf(v,  4.0f, -2.0f);
    return fmaf(v * v, pv, (u * u) * pu);
}

// cubic value + derivative: dc/dx = sign(x) * (6(u^2 - v^2) + 2(v - u))
__device__ __forceinline__ void cubic_cd(float x, float& c, float& d) {
    float ax = fabsf(x);
    float u = __saturatef(1.0f - ax);
    float v = __saturatef(fmaf(ax, -0.5f, 1.0f));
    float uu = u * u, vv = v * v;
    c = fmaf(vv, fmaf(v, 4.0f, -2.0f), uu * fmaf(u, -2.0f, 1.0f));
    float h = fmaf(uu - vv, 6.0f, 2.0f * (v - u));
    d = copysignf(h, x);
}

__global__ __launch_bounds__(TPB)
void kest_kernel(const float* __restrict__ m,
                 const float* __restrict__ grid,
                 const int*   __restrict__ Wp,
                 const int*   __restrict__ yi,
                 float*       __restrict__ out,
                 int N)
{
    __shared__ float w_s[TPB * KK];   // [pixel][49], stride 49 (odd -> conflict-free)
    __shared__ float inv_s[TPB];

    const int t = threadIdx.x;
    const int n = blockIdx.x * TPB + t;

    if (n < N) {
        const float m00 = __ldg(m + 0), m01 = __ldg(m + 1), m02 = __ldg(m + 2);
        const float m10 = __ldg(m + 3), m11 = __ldg(m + 4), m12 = __ldg(m + 5);
        const float m20 = __ldg(m + 6), m21 = __ldg(m + 7), m22 = __ldg(m + 8);
        const unsigned W = (unsigned)__ldg(Wp);

        const unsigned p = (unsigned)__ldg(yi + n);
        unsigned pxi, pyi_;
        if ((W & (W - 1u)) == 0u) {
            const int sh = __ffs((int)W) - 1;
            pxi = p & (W - 1u);
            pyi_ = p >> sh;
        } else {
            pyi_ = p / W;
            pxi = p - pyi_ * W;
        }
        const float px = (float)pxi;
        const float py = (float)pyi_;

        // Analytic central differences of the homography map:
        //   du = pb - pt = ((m01*Z0 - m21*X0), (m11*Z0 - m21*Y0)) / (Z0^2 - 0.25*m21^2)
        //   dv = pr - pl = ((m00*Z0 - m20*X0), (m10*Z0 - m20*Y0)) / (Z0^2 - 0.25*m20^2)
        const float X0 = fmaf(m00, px, fmaf(m01, py, m02));
        const float Y0 = fmaf(m10, px, fmaf(m11, py, m12));
        const float Z0 = fmaf(m20, px, fmaf(m21, py, m22));
        const float Z2 = Z0 * Z0;
        const float idu = 1.0f / fmaf(m21, -0.25f * m21, Z2);
        const float idv = 1.0f / fmaf(m20, -0.25f * m20, Z2);

        float du0 = (m01 * Z0 - m21 * X0) * idu;
        float du1 = (m11 * Z0 - m21 * Y0) * idu;
        float dv0 = (m00 * Z0 - m20 * X0) * idv;
        float dv1 = (m10 * Z0 - m20 * Y0) * idv;

        float len_du = sqrtf(du0 * du0 + du1 * du1);
        if (len_du < 1.0f) { du0 /= len_du; du1 /= len_du; len_du = 1.0f; }
        float len_dv = sqrtf(dv0 * dv0 + dv1 * dv1);
        if (len_dv < 1.0f) { dv0 /= len_dv; dv1 /= len_dv; len_dv = 1.0f; }

        const float det = du0 * dv1 - du1 * dv0;
        const float ild = 1.0f / (len_du * det);
        const float ilv = 1.0f / (len_dv * det);

        // x[ky][kx] = Axx*wx[kx] + Axy*wy[ky] ; y[ky][kx] = Cxx*wx[kx] + Dyy*wy[ky]
        const float Axx = du0 * dv1 * ild - du1 * dv0 * ilv;
        const float Axy = du0 * du1 * (ilv - ild);
        const float Cxx = dv0 * dv1 * (ild - ilv);
        const float Dyy = dv1 * du0 * ilv - dv0 * du1 * ild;

        const float gx = __ldg(grid + n);
        const float gy = __ldg(grid + N + n);
        const float posx = gx + 0.5f;
        const float posy = gy + 0.5f;
        const float fx = posx - floorf(posx);
        const float fy = posy - floorf(posy);

        float sum0 = 0.0f, sum1 = 0.0f;
        float* wrow = &w_s[t * KK];

        // cross-term magnitude bound: |B| <= 3.5|Axy|, |C| <= 3.5|Cxx|
        const float cross = fmaxf(fabsf(Axy), fabsf(Cxx)) * 3.5f;

        if (cross < 2e-3f) {
            // ---- fast path: 1st-order Taylor in the tiny cross terms ----
            // cubic(A[kx]+B[ky]) ~= cx[kx] + B[ky]*dx[kx]   (err <= 2.5*B^2 < 1e-5)
            // cubic(C[kx]+D[ky]) ~= cy[ky] + C[kx]*dy[ky]
            float cx[KS], dx[KS], Cv[KS];
            #pragma unroll
            for (int k = 0; k < KS; k++) {
                float wxk = fx + 2.5f - (float)k;
                cubic_cd(Axx * wxk, cx[k], dx[k]);
                Cv[k] = Cxx * wxk;
            }
            #pragma unroll
            for (int ky = 0; ky < KS; ky++) {
                float wyk = fy + 2.5f - (float)ky;
                float Bk = Axy * wyk;
                float cyk, dyk;
                cubic_cd(Dyy * wyk, cyk, dyk);
                #pragma unroll
                for (int kx = 0; kx < KS; kx++) {
                    float cxv = fmaf(Bk, dx[kx], cx[kx]);
                    float cyv = fmaf(Cv[kx], dyk, cyk);
                    float w = cxv * cyv;
                    if (kx & 1) sum1 += w; else sum0 += w;
                    wrow[ky * KS + kx] = w;
                }
            }
        } else {
            // ---- exact fallback (rare / never for near-identity homographies) ----
            float A[KS], Cc[KS];
            #pragma unroll
            for (int k = 0; k < KS; k++) {
                float wxk = fx + 2.5f - (float)k;
                A[k] = Axx * wxk;
                Cc[k] = Cxx * wxk;
            }
            #pragma unroll
            for (int ky = 0; ky < KS; ky++) {
                float wyk = fy + 2.5f - (float)ky;
                float Bk = Axy * wyk;
                float Dk = Dyy * wyk;
                #pragma unroll
                for (int kx = 0; kx < KS; kx++) {
                    float w = cubic_w(A[kx] + Bk) * cubic_w(Cc[kx] + Dk);
                    if (kx & 1) sum1 += w; else sum0 += w;
                    wrow[ky * KS + kx] = w;
                }
            }
        }
        inv_s[t] = 1.0f / (sum0 + sum1);
    }

    __syncthreads();

    // Coalesced vectorized write-out; SMEM already in output order for this block.
    const long long base = (long long)blockIdx.x * (TPB * KK);
    const int valid_pix = min(TPB, N - blockIdx.x * TPB);
    if (valid_pix <= 0) return;
    const int count = valid_pix * KK;
    const int n4 = count >> 2;

    const float4* s4 = (const float4*)w_s;
    float4* o4 = (float4*)(out + base);

    for (int f = t; f < n4; f += TPB) {
        float4 v = s4[f];
        unsigned i0 = 4u * (unsigned)f;
        unsigned q = i0 / 49u;
        unsigned r = i0 - q * 49u;
        float inv0 = inv_s[q];
        float inv1 = inv_s[q + (r >= 48u)];
        float inv2 = inv_s[q + (r >= 47u)];
        float inv3 = inv_s[q + (r >= 46u)];
        v.x *= inv0; v.y *= inv1; v.z *= inv2; v.w *= inv3;
        o4[f] = v;
    }
    for (int i = (n4 << 2) + t; i < count; i += TPB) {
        out[base + i] = w_s[i] * inv_s[(unsigned)i / 49u];
    }
}

extern "C" void kernel_launch(void* const* d_in, const int* in_sizes, int n_in,
                              void* d_out, int out_size) {
    // metadata order: m_inverse (9), grid (2N), H (1), W (1), yi (N)
    const float* m    = (const float*)d_in[0];
    const float* grid = (const float*)d_in[1];
    const int*   Wp   = (const int*)d_in[3];
    const int*   yi   = (const int*)d_in[4];
    float* out = (float*)d_out;

    const int N = in_sizes[4];
    const int blocks = (N + TPB - 1) / TPB;
    kest_kernel<<<blocks, TPB>>>(m, grid, Wp, yi, out, N);
}

// round 4
// speedup vs baseline: 1.5178x; 1.1858x over previous
#include <cuda_runtime.h>
#include <cuda_bf16.h>

#define KS 7
#define KK 49
#define TPB 128

typedef unsigned long long u64;

// ---- packed f32x2 helpers (sm_103a FFMA2/FMUL2 path) ----
__device__ __forceinline__ u64 pk2(float lo, float hi) {
    u64 r; asm("mov.b64 %0, {%1, %2};" : "=l"(r) : "f"(lo), "f"(hi)); return r;
}
__device__ __forceinline__ void unpk2(u64 a, float& lo, float& hi) {
    asm("mov.b64 {%0, %1}, %2;" : "=f"(lo), "=f"(hi) : "l"(a));
}
__device__ __forceinline__ u64 fma2(u64 a, u64 b, u64 c) {
    u64 d; asm("fma.rn.f32x2 %0, %1, %2, %3;" : "=l"(d) : "l"(a), "l"(b), "l"(c)); return d;
}
__device__ __forceinline__ u64 mul2(u64 a, u64 b) {
    u64 d; asm("mul.rn.f32x2 %0, %1, %2;" : "=l"(d) : "l"(a), "l"(b)); return d;
}

// Keys bicubic (a=-0.5), branch-free: cubic(x) = u^2(1-2u) + v^2(4v-2),
// u = sat(1-|x|), v = sat(1-|x|/2). C1-continuous.
__device__ __forceinline__ float cubic_w(float x) {
    float ax = fabsf(x);
    float u = __saturatef(1.0f - ax);
    float v = __saturatef(fmaf(ax, -0.5f, 1.0f));
    return fmaf(v * v, fmaf(v, 4.0f, -2.0f), (u * u) * fmaf(u, -2.0f, 1.0f));
}

// cubic value + derivative: dc/dx = sign(x) * (6(u^2 - v^2) + 2(v - u))
__device__ __forceinline__ void cubic_cd(float x, float& c, float& d) {
    float ax = fabsf(x);
    float u = __saturatef(1.0f - ax);
    float v = __saturatef(fmaf(ax, -0.5f, 1.0f));
    float uu = u * u, vv = v * v;
    c = fmaf(vv, fmaf(v, 4.0f, -2.0f), uu * fmaf(u, -2.0f, 1.0f));
    float h = fmaf(uu - vv, 6.0f, 2.0f * (v - u));
    d = copysignf(h, x);
}

__global__ __launch_bounds__(TPB)
void kest_kernel(const float* __restrict__ m,
                 const float* __restrict__ grid,
                 const int*   __restrict__ Wp,
                 const int*   __restrict__ yi,
                 float*       __restrict__ out,
                 int N)
{
    __shared__ __align__(16) float w_s[TPB * KK];  // NORMALIZED weights, output order

    const int t = threadIdx.x;
    const int n = blockIdx.x * TPB + t;

    if (n < N) {
        const float m00 = __ldg(m + 0), m01 = __ldg(m + 1), m02 = __ldg(m + 2);
        const float m10 = __ldg(m + 3), m11 = __ldg(m + 4), m12 = __ldg(m + 5);
        const float m20 = __ldg(m + 6), m21 = __ldg(m + 7), m22 = __ldg(m + 8);
        const unsigned W = (unsigned)__ldg(Wp);

        const unsigned p = (unsigned)__ldg(yi + n);
        unsigned pxi, pyi_;
        if ((W & (W - 1u)) == 0u) {
            const int sh = __ffs((int)W) - 1;
            pxi = p & (W - 1u);
            pyi_ = p >> sh;
        } else {
            pyi_ = p / W;
            pxi = p - pyi_ * W;
        }
        const float px = (float)pxi;
        const float py = (float)pyi_;

        // Analytic central differences of the homography map
        const float X0 = fmaf(m00, px, fmaf(m01, py, m02));
        const float Y0 = fmaf(m10, px, fmaf(m11, py, m12));
        const float Z0 = fmaf(m20, px, fmaf(m21, py, m22));
        const float Z2 = Z0 * Z0;
        const float idu = 1.0f / fmaf(m21, -0.25f * m21, Z2);
        const float idv = 1.0f / fmaf(m20, -0.25f * m20, Z2);

        float du0 = (m01 * Z0 - m21 * X0) * idu;
        float du1 = (m11 * Z0 - m21 * Y0) * idu;
        float dv0 = (m00 * Z0 - m20 * X0) * idv;
        float dv1 = (m10 * Z0 - m20 * Y0) * idv;

        float len_du = sqrtf(du0 * du0 + du1 * du1);
        if (len_du < 1.0f) { du0 /= len_du; du1 /= len_du; len_du = 1.0f; }
        float len_dv = sqrtf(dv0 * dv0 + dv1 * dv1);
        if (len_dv < 1.0f) { dv0 /= len_dv; dv1 /= len_dv; len_dv = 1.0f; }

        const float det = du0 * dv1 - du1 * dv0;
        const float ild = 1.0f / (len_du * det);
        const float ilv = 1.0f / (len_dv * det);

        const float Axx = du0 * dv1 * ild - du1 * dv0 * ilv;
        const float Axy = du0 * du1 * (ilv - ild);
        const float Cxx = dv0 * dv1 * (ild - ilv);
        const float Dyy = dv1 * du0 * ilv - dv0 * du1 * ild;

        const float gx = __ldg(grid + n);
        const float gy = __ldg(grid + N + n);
        const float fx = (gx + 0.5f) - floorf(gx + 0.5f);
        const float fy = (gy + 0.5f) - floorf(gy + 0.5f);

        float* wrow = &w_s[t * KK];
        const float cross = fmaxf(fabsf(Axy), fabsf(Cxx)) * 3.5f;

        if (cross < 2e-3f) {
            // ---- fast path: Taylor in tiny cross terms, factored sum ----
            float cx[KS], dx[KS], Cv[KS];
            float Scx = 0.0f, Sdx = 0.0f, Scxc = 0.0f, Sdxc = 0.0f;
            #pragma unroll
            for (int k = 0; k < KS; k++) {
                float wxk = fx + 2.5f - (float)k;
                cubic_cd(Axx * wxk, cx[k], dx[k]);
                Cv[k] = Cxx * wxk;
                Scx += cx[k];
                Sdx += dx[k];
                Scxc = fmaf(cx[k], Cv[k], Scxc);
                Sdxc = fmaf(dx[k], Cv[k], Sdxc);
            }

            float By[KS], cy[KS], dy[KS];
            float sum = 0.0f;
            #pragma unroll
            for (int k = 0; k < KS; k++) {
                float wyk = fy + 2.5f - (float)k;
                cubic_cd(Dyy * wyk, cy[k], dy[k]);
                By[k] = Axy * wyk;
                // sum += cy*(Scx + By*Sdx) + dy*(Scxc + By*Sdxc)
                sum = fmaf(cy[k], fmaf(By[k], Sdx, Scx),
                      fmaf(dy[k], fmaf(By[k], Sdxc, Scxc), sum));
            }
            const float inv = 1.0f / sum;
            #pragma unroll
            for (int k = 0; k < KS; k++) { cy[k] *= inv; dy[k] *= inv; }

            // packed element loop: w = (cx + B*dx) * (cy' + Cv*dy')
            u64 cx2[3], dx2[3], Cv2[3];
            #pragma unroll
            for (int j = 0; j < 3; j++) {
                cx2[j] = pk2(cx[2*j], cx[2*j+1]);
                dx2[j] = pk2(dx[2*j], dx[2*j+1]);
                Cv2[j] = pk2(Cv[2*j], Cv[2*j+1]);
            }
            #pragma unroll
            for (int ky = 0; ky < KS; ky++) {
                u64 B2  = pk2(By[ky], By[ky]);
                u64 cy2 = pk2(cy[ky], cy[ky]);
                u64 dy2 = pk2(dy[ky], dy[ky]);
                float* r = wrow + ky * KS;
                #pragma unroll
                for (int j = 0; j < 3; j++) {
                    u64 a = fma2(B2, dx2[j], cx2[j]);
                    u64 b = fma2(Cv2[j], dy2, cy2);
                    u64 w2 = mul2(a, b);
                    float wl, wh; unpk2(w2, wl, wh);
                    r[2*j]   = wl;
                    r[2*j+1] = wh;
                }
                float a6 = fmaf(By[ky], dx[6], cx[6]);
                float b6 = fmaf(Cv[6], dy[ky], cy[ky]);
                r[6] = a6 * b6;
            }
        } else {
            // ---- exact fallback (not taken for near-identity homographies) ----
            float A[KS], Cc[KS];
            #pragma unroll
            for (int k = 0; k < KS; k++) {
                float wxk = fx + 2.5f - (float)k;
                A[k] = Axx * wxk;
                Cc[k] = Cxx * wxk;
            }
            float sum = 0.0f;
            #pragma unroll
            for (int ky = 0; ky < KS; ky++) {
                float wyk = fy + 2.5f - (float)ky;
                float Bk = Axy * wyk;
                float Dk = Dyy * wyk;
                #pragma unroll
                for (int kx = 0; kx < KS; kx++) {
                    float w = cubic_w(A[kx] + Bk) * cubic_w(Cc[kx] + Dk);
                    sum += w;
                    wrow[ky * KS + kx] = w;
                }
            }
            const float inv = 1.0f / sum;
            #pragma unroll
            for (int j = 0; j < KK; j++) wrow[j] *= inv;
        }
    }

    __syncthreads();

    // ---- write-out: one bulk async copy SMEM -> GMEM (already normalized, output order)
    const long long base = (long long)blockIdx.x * (TPB * KK);
    const int valid_pix = min(TPB, N - blockIdx.x * TPB);
    if (valid_pix <= 0) return;
    const int count = valid_pix * KK;

    if ((count & 3) == 0) {
        if (t == 0) {
            unsigned saddr = (unsigned)__cvta_generic_to_shared(w_s);
            asm volatile("fence.proxy.async.shared::cta;" ::: "memory");
            asm volatile("cp.async.bulk.global.shared::cta.bulk_group [%0], [%1], %2;"
                         :: "l"(out + base), "r"(saddr), "r"((unsigned)(count * 4))
                         : "memory");
            asm volatile("cp.async.bulk.commit_group;" ::: "memory");
            asm volatile("cp.async.bulk.wait_group 0;" ::: "memory");
        }
    } else {
        for (int i = t; i < count; i += TPB) out[base + i] = w_s[i];
    }
}

extern "C" void kernel_launch(void* const* d_in, const int* in_sizes, int n_in,
                              void* d_out, int out_size) {
    // metadata order: m_inverse (9), grid (2N), H (1), W (1), yi (N)
    const float* m    = (const float*)d_in[0];
    const float* grid = (const float*)d_in[1];
    const int*   Wp   = (const int*)d_in[3];
    const int*   yi   = (const int*)d_in[4];
    float* out = (float*)d_out;

    const int N = in_sizes[4];
    const int blocks = (N + TPB - 1) / TPB;
    kest_kernel<<<blocks, TPB>>>(m, grid, Wp, yi, out, N);
}

// round 5
// speedup vs baseline: 1.6410x; 1.0812x over previous
#include <cuda_runtime.h>
#include <cuda_bf16.h>

#define KS 7
#define KK 49
#define TPB 128

typedef unsigned long long u64;

// ---- packed f32x2 helpers (sm_103a FFMA2/FMUL2) ----
__device__ __forceinline__ u64 pk2(float lo, float hi) {
    u64 r; asm("mov.b64 %0, {%1, %2};" : "=l"(r) : "f"(lo), "f"(hi)); return r;
}
__device__ __forceinline__ void unpk2(u64 a, float& lo, float& hi) {
    asm("mov.b64 {%0, %1}, %2;" : "=f"(lo), "=f"(hi) : "l"(a));
}
__device__ __forceinline__ u64 fma2(u64 a, u64 b, u64 c) {
    u64 d; asm("fma.rn.f32x2 %0, %1, %2, %3;" : "=l"(d) : "l"(a), "l"(b), "l"(c)); return d;
}
__device__ __forceinline__ u64 mul2(u64 a, u64 b) {
    u64 d; asm("mul.rn.f32x2 %0, %1, %2;" : "=l"(d) : "l"(a), "l"(b)); return d;
}

// Keys bicubic (a=-0.5), branch-free: cubic(x) = u^2(1-2u) + v^2(4v-2),
// u = sat(1-|x|), v = sat(1-|x|/2). C1-continuous.
__device__ __forceinline__ float cubic_w(float x) {
    float ax = fabsf(x);
    float u = __saturatef(1.0f - ax);
    float v = __saturatef(fmaf(ax, -0.5f, 1.0f));
    return fmaf(v * v, fmaf(v, 4.0f, -2.0f), (u * u) * fmaf(u, -2.0f, 1.0f));
}

// cubic value + derivative: dc/dx = sign(x) * (6(u^2 - v^2) + 2(v - u))
__device__ __forceinline__ void cubic_cd(float x, float& c, float& d) {
    float ax = fabsf(x);
    float u = __saturatef(1.0f - ax);
    float v = __saturatef(fmaf(ax, -0.5f, 1.0f));
    float uu = u * u, vv = v * v;
    c = fmaf(vv, fmaf(v, 4.0f, -2.0f), uu * fmaf(u, -2.0f, 1.0f));
    float h = fmaf(uu - vv, 6.0f, 2.0f * (v - u));
    d = copysignf(h, x);
}

__global__ __launch_bounds__(TPB, 8)
void kest_kernel(const float* __restrict__ m,
                 const float* __restrict__ grid,
                 const int*   __restrict__ Wp,
                 const int*   __restrict__ yi,
                 float*       __restrict__ out,
                 int N)
{
    __shared__ __align__(16) float w_s[TPB * KK];  // NORMALIZED weights, output order

    const int t = threadIdx.x;
    const int n = blockIdx.x * TPB + t;

    if (n < N) {
        const float m00 = __ldg(m + 0), m01 = __ldg(m + 1), m02 = __ldg(m + 2);
        const float m10 = __ldg(m + 3), m11 = __ldg(m + 4), m12 = __ldg(m + 5);
        const float m20 = __ldg(m + 6), m21 = __ldg(m + 7), m22 = __ldg(m + 8);
        const unsigned W = (unsigned)__ldg(Wp);

        const unsigned p = (unsigned)__ldg(yi + n);
        unsigned pxi, pyi_;
        if ((W & (W - 1u)) == 0u) {           // uniform branch
            const int sh = __ffs((int)W) - 1;
            pxi = p & (W - 1u);
            pyi_ = p >> sh;
        } else {
            pyi_ = p / W;
            pxi = p - pyi_ * W;
        }
        const float px = (float)pxi;
        const float py = (float)pyi_;

        // Analytic central differences of the homography map
        const float X0 = fmaf(m00, px, fmaf(m01, py, m02));
        const float Y0 = fmaf(m10, px, fmaf(m11, py, m12));
        const float Z0 = fmaf(m20, px, fmaf(m21, py, m22));
        const float Z2 = Z0 * Z0;
        const float idu = __fdividef(1.0f, fmaf(m21, -0.25f * m21, Z2));
        const float idv = __fdividef(1.0f, fmaf(m20, -0.25f * m20, Z2));

        float du0 = (m01 * Z0 - m21 * X0) * idu;
        float du1 = (m11 * Z0 - m21 * Y0) * idu;
        float dv0 = (m00 * Z0 - m20 * X0) * idv;
        float dv1 = (m10 * Z0 - m20 * Y0) * idv;

        // branch-free |du| >= 1 regularization via rsqrt
        {
            float s = fmaf(du0, du0, du1 * du1);
            float rs = __frsqrt_rn(s);
            float len = s * rs;                 // sqrt(s)
            bool c = len < 1.0f;
            float sc = c ? rs : 1.0f;
            du0 *= sc; du1 *= sc;
            float len_du = c ? 1.0f : len;

            float s2 = fmaf(dv0, dv0, dv1 * dv1);
            float rs2 = __frsqrt_rn(s2);
            float len2 = s2 * rs2;
            bool c2 = len2 < 1.0f;
            float sc2 = c2 ? rs2 : 1.0f;
            dv0 *= sc2; dv1 *= sc2;
            float len_dv = c2 ? 1.0f : len2;

            const float det = du0 * dv1 - du1 * dv0;
            const float ild = __fdividef(1.0f, len_du * det);
            const float ilv = __fdividef(1.0f, len_dv * det);

            const float Axx = du0 * dv1 * ild - du1 * dv0 * ilv;
            const float Axy = du0 * du1 * (ilv - ild);
            const float Cxx = dv0 * dv1 * (ild - ilv);
            const float Dyy = dv1 * du0 * ilv - dv0 * du1 * ild;

            const float gx = __ldg(grid + n);
            const float gy = __ldg(grid + N + n);
            const float fx = (gx + 0.5f) - floorf(gx + 0.5f);
            const float fy = (gy + 0.5f) - floorf(gy + 0.5f);

            float* wrow = &w_s[t * KK];
            const float cross = fmaxf(fabsf(Axy), fabsf(Cxx)) * 3.5f;

            if (cross < 2e-3f) {
                // ---- phase A: packed x-direction tables + factored partial sums ----
                u64 cx2[3], dx2[3], Cv2[3];
                float cx6, dx6, Cv6;
                float Scx, Sdx, Scxc, Sdxc;
                {
                    float c0, d0, c1, d1;
                    float w0 = fx + 2.5f;          // k=0
                    float w1 = fx + 1.5f;          // k=1
                    cubic_cd(Axx * w0, c0, d0);
                    cubic_cd(Axx * w1, c1, d1);
                    float v0 = Cxx * w0, v1 = Cxx * w1;
                    cx2[0] = pk2(c0, c1); dx2[0] = pk2(d0, d1); Cv2[0] = pk2(v0, v1);
                    Scx = c0 + c1; Sdx = d0 + d1;
                    Scxc = fmaf(c0, v0, c1 * v1);
                    Sdxc = fmaf(d0, v0, d1 * v1);

                    w0 = fx + 0.5f; w1 = fx - 0.5f;     // k=2,3
                    cubic_cd(Axx * w0, c0, d0);
                    cubic_cd(Axx * w1, c1, d1);
                    v0 = Cxx * w0; v1 = Cxx * w1;
                    cx2[1] = pk2(c0, c1); dx2[1] = pk2(d0, d1); Cv2[1] = pk2(v0, v1);
                    Scx += c0 + c1; Sdx += d0 + d1;
                    Scxc = fmaf(c0, v0, fmaf(c1, v1, Scxc));
                    Sdxc = fmaf(d0, v0, fmaf(d1, v1, Sdxc));

                    w0 = fx - 1.5f; w1 = fx - 2.5f;     // k=4,5
                    cubic_cd(Axx * w0, c0, d0);
                    cubic_cd(Axx * w1, c1, d1);
                    v0 = Cxx * w0; v1 = Cxx * w1;
                    cx2[2] = pk2(c0, c1); dx2[2] = pk2(d0, d1); Cv2[2] = pk2(v0, v1);
                    Scx += c0 + c1; Sdx += d0 + d1;
                    Scxc = fmaf(c0, v0, fmaf(c1, v1, Scxc));
                    Sdxc = fmaf(d0, v0, fmaf(d1, v1, Sdxc));

                    float w6 = fx - 3.5f;               // k=6
                    cubic_cd(Axx * w6, cx6, dx6);
                    Cv6 = Cxx * w6;
                    Scx += cx6; Sdx += dx6;
                    Scxc = fmaf(cx6, Cv6, Scxc);
                    Sdxc = fmaf(dx6, Cv6, Sdxc);
                }

                // ---- phase B: factored sum over y (no arrays kept) ----
                float sum = 0.0f;
                #pragma unroll
                for (int k = 0; k < KS; k++) {
                    float wyk = fy + 2.5f - (float)k;
                    float cy, dy;
                    cubic_cd(Dyy * wyk, cy, dy);
                    float By = Axy * wyk;
                    sum = fmaf(cy, fmaf(By, Sdx, Scx),
                          fmaf(dy, fmaf(By, Sdxc, Scxc), sum));
                }
                const float inv = __fdividef(1.0f, sum);

                // ---- element loop: recompute y terms, write normalized weights ----
                #pragma unroll
                for (int ky = 0; ky < KS; ky++) {
                    float wyk = fy + 2.5f - (float)ky;
                    float cy, dy;
                    cubic_cd(Dyy * wyk, cy, dy);
                    float By = Axy * wyk;
                    cy *= inv; dy *= inv;
                    u64 B2  = pk2(By, By);
                    u64 cy2 = pk2(cy, cy);
                    u64 dy2 = pk2(dy, dy);
                    float* r = wrow + ky * KS;
                    #pragma unroll
                    for (int j = 0; j < 3; j++) {
                        u64 a  = fma2(B2, dx2[j], cx2[j]);
                        u64 b  = fma2(Cv2[j], dy2, cy2);
                        u64 w2 = mul2(a, b);
                        float wl, wh; unpk2(w2, wl, wh);
                        r[2*j]   = wl;
                        r[2*j+1] = wh;
                    }
                    r[6] = fmaf(By, dx6, cx6) * fmaf(Cv6, dy, cy);
                }
            } else {
                // ---- exact fallback (not taken for near-identity homographies) ----
                float A[KS], Cc[KS];
                #pragma unroll
                for (int k = 0; k < KS; k++) {
                    float wxk = fx + 2.5f - (float)k;
                    A[k] = Axx * wxk;
                    Cc[k] = Cxx * wxk;
                }
                float sum = 0.0f;
                #pragma unroll
                for (int ky = 0; ky < KS; ky++) {
                    float wyk = fy + 2.5f - (float)ky;
                    float Bk = Axy * wyk;
                    float Dk = Dyy * wyk;
                    #pragma unroll
                    for (int kx = 0; kx < KS; kx++) {
                        float w = cubic_w(A[kx] + Bk) * cubic_w(Cc[kx] + Dk);
                        sum += w;
                        wrow[ky * KS + kx] = w;
                    }
                }
                const float inv = __fdividef(1.0f, sum);
                #pragma unroll
                for (int j = 0; j < KK; j++) wrow[j] *= inv;
            }
        }
    }

    __syncthreads();

    // ---- write-out: one bulk async copy SMEM -> GMEM ----
    const long long base = (long long)blockIdx.x * (TPB * KK);
    const int valid_pix = min(TPB, N - blockIdx.x * TPB);
    if (valid_pix <= 0) return;
    const int count = valid_pix * KK;

    if ((count & 3) == 0) {
        if (t == 0) {
            unsigned saddr = (unsigned)__cvta_generic_to_shared(w_s);
            asm volatile("fence.proxy.async.shared::cta;" ::: "memory");
            asm volatile("cp.async.bulk.global.shared::cta.bulk_group [%0], [%1], %2;"
                         :: "l"(out + base), "r"(saddr), "r"((unsigned)(count * 4))
                         : "memory");
            asm volatile("cp.async.bulk.commit_group;" ::: "memory");
            asm volatile("cp.async.bulk.wait_group 0;" ::: "memory");
        }
    } else {
        for (int i = t; i < count; i += TPB) out[base + i] = w_s[i];
    }
}

extern "C" void kernel_launch(void* const* d_in, const int* in_sizes, int n_in,
                              void* d_out, int out_size) {
    // metadata order: m_inverse (9), grid (2N), H (1), W (1), yi (N)
    const float* m    = (const float*)d_in[0];
    const float* grid = (const float*)d_in[1];
    const int*   Wp   = (const int*)d_in[3];
    const int*   yi   = (const int*)d_in[4];
    float* out = (float*)d_out;

    const int N = in_sizes[4];
    const int blocks = (N + TPB - 1) / TPB;
    kest_kernel<<<blocks, TPB>>>(m, grid, Wp, yi, out, N);
}

// round 6
// speedup vs baseline: 1.6523x; 1.0069x over previous
#include <cuda_runtime.h>
#include <cuda_bf16.h>

#define KS 7
#define KK 49
#define TPB 128

typedef unsigned long long u64;

// ---- packed f32x2 helpers (sm_103a FFMA2/FMUL2) ----
__device__ __forceinline__ u64 pk2(float lo, float hi) {
    u64 r; asm("mov.b64 %0, {%1, %2};" : "=l"(r) : "f"(lo), "f"(hi)); return r;
}
__device__ __forceinline__ void unpk2(u64 a, float& lo, float& hi) {
    asm("mov.b64 {%0, %1}, %2;" : "=f"(lo), "=f"(hi) : "l"(a));
}
__device__ __forceinline__ u64 fma2(u64 a, u64 b, u64 c) {
    u64 d; asm("fma.rn.f32x2 %0, %1, %2, %3;" : "=l"(d) : "l"(a), "l"(b), "l"(c)); return d;
}
__device__ __forceinline__ u64 mul2(u64 a, u64 b) {
    u64 d; asm("mul.rn.f32x2 %0, %1, %2;" : "=l"(d) : "l"(a), "l"(b)); return d;
}

// Keys bicubic (a=-0.5), branch-free: cubic(x) = u^2(1-2u) + v^2(4v-2),
// u = sat(1-|x|), v = sat(1-|x|/2). C1-continuous, zero for |x|>=2.
__device__ __forceinline__ float cubic_w(float x) {
    float ax = fabsf(x);
    float u = __saturatef(1.0f - ax);
    float v = __saturatef(fmaf(ax, -0.5f, 1.0f));
    return fmaf(v * v, fmaf(v, 4.0f, -2.0f), (u * u) * fmaf(u, -2.0f, 1.0f));
}

// cubic value + derivative: dc/dx = sign(x) * (6(u^2 - v^2) + 2(v - u))
__device__ __forceinline__ void cubic_cd(float x, float& c, float& d) {
    float ax = fabsf(x);
    float u = __saturatef(1.0f - ax);
    float v = __saturatef(fmaf(ax, -0.5f, 1.0f));
    float uu = u * u, vv = v * v;
    c = fmaf(vv, fmaf(v, 4.0f, -2.0f), uu * fmaf(u, -2.0f, 1.0f));
    float h = fmaf(uu - vv, 6.0f, 2.0f * (v - u));
    d = copysignf(h, x);
}

__global__ __launch_bounds__(TPB, 8)
void kest_kernel(const float* __restrict__ m,
                 const float* __restrict__ grid,
                 const int*   __restrict__ Wp,
                 const int*   __restrict__ yi,
                 float*       __restrict__ out,
                 int N)
{
    __shared__ __align__(16) float w_s[TPB * KK];  // NORMALIZED weights, output order

    const int t = threadIdx.x;
    const int n = blockIdx.x * TPB + t;

    if (n < N) {
        const float m00 = __ldg(m + 0), m01 = __ldg(m + 1), m02 = __ldg(m + 2);
        const float m10 = __ldg(m + 3), m11 = __ldg(m + 4), m12 = __ldg(m + 5);
        const float m20 = __ldg(m + 6), m21 = __ldg(m + 7), m22 = __ldg(m + 8);
        const unsigned W = (unsigned)__ldg(Wp);

        const unsigned p = (unsigned)__ldg(yi + n);
        unsigned pxi, pyi_;
        if ((W & (W - 1u)) == 0u) {           // uniform branch
            const int sh = __ffs((int)W) - 1;
            pxi = p & (W - 1u);
            pyi_ = p >> sh;
        } else {
            pyi_ = p / W;
            pxi = p - pyi_ * W;
        }
        const float px = (float)pxi;
        const float py = (float)pyi_;

        // Analytic central differences of the homography map
        const float X0 = fmaf(m00, px, fmaf(m01, py, m02));
        const float Y0 = fmaf(m10, px, fmaf(m11, py, m12));
        const float Z0 = fmaf(m20, px, fmaf(m21, py, m22));
        const float Z2 = Z0 * Z0;
        const float idu = __fdividef(1.0f, fmaf(m21, -0.25f * m21, Z2));
        const float idv = __fdividef(1.0f, fmaf(m20, -0.25f * m20, Z2));

        float du0 = (m01 * Z0 - m21 * X0) * idu;
        float du1 = (m11 * Z0 - m21 * Y0) * idu;
        float dv0 = (m00 * Z0 - m20 * X0) * idv;
        float dv1 = (m10 * Z0 - m20 * Y0) * idv;

        // branch-free |du| >= 1 regularization via rsqrt
        float s = fmaf(du0, du0, du1 * du1);
        float rs = __frsqrt_rn(s);
        float len = s * rs;
        bool cnd = len < 1.0f;
        float sc = cnd ? rs : 1.0f;
        du0 *= sc; du1 *= sc;
        float len_du = cnd ? 1.0f : len;

        float s2 = fmaf(dv0, dv0, dv1 * dv1);
        float rs2 = __frsqrt_rn(s2);
        float len2 = s2 * rs2;
        bool cnd2 = len2 < 1.0f;
        float sc2 = cnd2 ? rs2 : 1.0f;
        dv0 *= sc2; dv1 *= sc2;
        float len_dv = cnd2 ? 1.0f : len2;

        const float det = du0 * dv1 - du1 * dv0;
        const float ild = __fdividef(1.0f, len_du * det);
        const float ilv = __fdividef(1.0f, len_dv * det);

        const float Axx = du0 * dv1 * ild - du1 * dv0 * ilv;
        const float Axy = du0 * du1 * (ilv - ild);
        const float Cxx = dv0 * dv1 * (ild - ilv);
        const float Dyy = dv1 * du0 * ilv - dv0 * du1 * ild;

        const float gx = __ldg(grid + n);
        const float gy = __ldg(grid + N + n);
        const float fx = (gx + 0.5f) - floorf(gx + 0.5f);
        const float fy = (gy + 0.5f) - floorf(gy + 0.5f);

        float* wrow = &w_s[t * KK];
        const float cross = fmaxf(fabsf(Axy), fabsf(Cxx)) * 3.5f;
        // Fast path needs: tiny cross terms (Taylor) AND |Axx|,|Dyy| >= 0.85 so
        // taps 0 and 6 are provably in the cubic's zero region (0.85*2.5 = 2.125 > 2 + 2e-3 slop).
        const bool fast = (cross < 2e-3f) & (fabsf(Axx) >= 0.85f) & (fabsf(Dyy) >= 0.85f);

        if (fast) {
            // ---- 5x5 core: taps k=1..5 in both directions ----
            float cxk[5], dxk[5], Cvk[5];
            float Scx = 0.0f, Sdx = 0.0f, Scxc = 0.0f, Sdxc = 0.0f;
            #pragma unroll
            for (int i = 0; i < 5; i++) {
                float wxk = fx + 1.5f - (float)i;      // k = i+1
                cubic_cd(Axx * wxk, cxk[i], dxk[i]);
                Cvk[i] = Cxx * wxk;
                Scx += cxk[i];
                Sdx += dxk[i];
                Scxc = fmaf(cxk[i], Cvk[i], Scxc);
                Sdxc = fmaf(dxk[i], Cvk[i], Sdxc);
            }

            float cy[5], dy[5], By[5];
            float sum = 0.0f;
            #pragma unroll
            for (int i = 0; i < 5; i++) {
                float wyk = fy + 1.5f - (float)i;
                cubic_cd(Dyy * wyk, cy[i], dy[i]);
                By[i] = Axy * wyk;
                sum = fmaf(cy[i], fmaf(By[i], Sdx, Scx),
                      fmaf(dy[i], fmaf(By[i], Sdxc, Scxc), sum));
            }
            const float inv = __fdividef(1.0f, sum);

            // zero border: rows 0 and 6 (7 each), cols 0 and 6 of rows 1..5
            #pragma unroll
            for (int j = 0; j < KS; j++) { wrow[j] = 0.0f; wrow[42 + j] = 0.0f; }
            #pragma unroll
            for (int ky = 1; ky <= 5; ky++) { wrow[ky * KS] = 0.0f; wrow[ky * KS + 6] = 0.0f; }

            // packed x tables
            u64 cxA = pk2(cxk[0], cxk[1]), cxB = pk2(cxk[2], cxk[3]);
            u64 dxA = pk2(dxk[0], dxk[1]), dxB = pk2(dxk[2], dxk[3]);
            u64 CvA = pk2(Cvk[0], Cvk[1]), CvB = pk2(Cvk[2], Cvk[3]);

            // element loop: 5 rows x 5 cols, normalized
            #pragma unroll
            for (int i = 0; i < 5; i++) {
                float cyn = cy[i] * inv;
                float dyn = dy[i] * inv;
                u64 B2  = pk2(By[i], By[i]);
                u64 cy2 = pk2(cyn, cyn);
                u64 dy2 = pk2(dyn, dyn);
                float* r = wrow + (i + 1) * KS;
                u64 a  = fma2(B2, dxA, cxA);
                u64 b  = fma2(CvA, dy2, cy2);
                u64 w2 = mul2(a, b);
                float wl, wh; unpk2(w2, wl, wh);
                r[1] = wl; r[2] = wh;
                a  = fma2(B2, dxB, cxB);
                b  = fma2(CvB, dy2, cy2);
                w2 = mul2(a, b);
                unpk2(w2, wl, wh);
                r[3] = wl; r[4] = wh;
                r[5] = fmaf(By[i], dxk[4], cxk[4]) * fmaf(Cvk[4], dyn, cyn);
            }
        } else {
            // ---- exact fallback: full 7x7 ----
            float A[KS], Cc[KS];
            #pragma unroll
            for (int k = 0; k < KS; k++) {
                float wxk = fx + 2.5f - (float)k;
                A[k] = Axx * wxk;
                Cc[k] = Cxx * wxk;
            }
            float sum = 0.0f;
            #pragma unroll
            for (int ky = 0; ky < KS; ky++) {
                float wyk = fy + 2.5f - (float)ky;
                float Bk = Axy * wyk;
                float Dk = Dyy * wyk;
                #pragma unroll
                for (int kx = 0; kx < KS; kx++) {
                    float w = cubic_w(A[kx] + Bk) * cubic_w(Cc[kx] + Dk);
                    sum += w;
                    wrow[ky * KS + kx] = w;
                }
            }
            const float inv = __fdividef(1.0f, sum);
            #pragma unroll
            for (int j = 0; j < KK; j++) wrow[j] *= inv;
        }
    }

    __syncthreads();

    // ---- write-out: one bulk async copy SMEM -> GMEM ----
    const long long base = (long long)blockIdx.x * (TPB * KK);
    const int valid_pix = min(TPB, N - blockIdx.x * TPB);
    if (valid_pix <= 0) return;
    const int count = valid_pix * KK;

    if ((count & 3) == 0) {
        if (t == 0) {
            unsigned saddr = (unsigned)__cvta_generic_to_shared(w_s);
            asm volatile("fence.proxy.async.shared::cta;" ::: "memory");
            asm volatile("cp.async.bulk.global.shared::cta.bulk_group [%0], [%1], %2;"
                         :: "l"(out + base), "r"(saddr), "r"((unsigned)(count * 4))
                         : "memory");
            asm volatile("cp.async.bulk.commit_group;" ::: "memory");
            asm volatile("cp.async.bulk.wait_group 0;" ::: "memory");
        }
    } else {
        for (int i = t; i < count; i += TPB) out[base + i] = w_s[i];
    }
}

extern "C" void kernel_launch(void* const* d_in, const int* in_sizes, int n_in,
                              void* d_out, int out_size) {
    // metadata order: m_inverse (9), grid (2N), H (1), W (1), yi (N)
    const float* m    = (const float*)d_in[0];
    const float* grid = (const float*)d_in[1];
    const int*   Wp   = (const int*)d_in[3];
    const int*   yi   = (const int*)d_in[4];
    float* out = (float*)d_out;

    const int N = in_sizes[4];
    const int blocks = (N + TPB - 1) / TPB;
    kest_kernel<<<blocks, TPB>>>(m, grid, Wp, yi, out, N);
}